// round 8
// baseline (speedup 1.0000x reference)
#include <cuda_runtime.h>
#include <math.h>

#define BB 64
#define NN 16800
#define CC 21
#define TPB 256
#define NBLK 66          // ceil(16800/256)
#define FP32_EPS 1.1920928955078125e-07f
#define SBINS 1024       // stage-0 linear bins
#define CAPB  4096       // candidate buffer capacity

// ---------------- scratch (device globals; no allocation) ----------------
__device__ float d_neg [BB * NN];
__device__ float d_psl1[BB * NBLK];
__device__ float d_pce [BB * NBLK];
__device__ int   d_ppos[BB * NBLK];
__device__ float d_res [BB * 3];
__device__ int   d_btick[BB];             // per-batch ticket (self-resetting)
__device__ int   d_done;                  // cross-batch ticket (self-resetting)

__device__ __forceinline__ float smooth_l1(float d) {
    float a = fabsf(d);
    return (a < 1.f) ? (0.5f * a * a) : (a - 0.5f);
}

// linear equal-width bin over [0,32): ce population spreads over ~hundreds of bins
__device__ __forceinline__ unsigned lin_bin(float v) {
    return min((unsigned)(SBINS - 1), (unsigned)(v * 32.0f));
}

// Warp 0 (tid<32): suffix-scan 256 group sums, locate bin holding the k-th largest.
__device__ __forceinline__ void warp_locate(const unsigned* hist, const unsigned* gsum,
                                            int gper, int k,
                                            unsigned* o_sel, unsigned* o_krem) {
    const int lane = threadIdx.x;  // caller guarantees tid < 32
    unsigned g[8];
    unsigned p = 0;
    #pragma unroll
    for (int j = 0; j < 8; j++) { g[j] = gsum[lane * 8 + j]; p += g[j]; }
    unsigned sfx = p;
    #pragma unroll
    for (int o = 1; o < 32; o <<= 1) {
        unsigned v = __shfl_down_sync(0xFFFFFFFFu, sfx, o);
        if (lane + o < 32) sfx += v;
    }
    unsigned above = sfx - p;
    if (above < (unsigned)k && sfx >= (unsigned)k) {
        unsigned cum = above;
        #pragma unroll
        for (int j = 7; j >= 0; j--) {
            unsigned gj = g[j];
            if (cum + gj >= (unsigned)k) {
                const int bbase = (lane * 8 + j) * gper;
                for (int q = gper - 1; q >= 0; q--) {
                    unsigned h = hist[bbase + q];
                    if (cum + h >= (unsigned)k) {
                        *o_sel  = (unsigned)(bbase + q);
                        *o_krem = (unsigned)k - cum;
                        return;
                    }
                    cum += h;
                }
            }
            cum += gj;
        }
    }
}

// ---------------- fused kernel: main work + per-batch tail selection ----------------
__global__ void __launch_bounds__(TPB, 8)
k_all(const float4* __restrict__ pb,
      const float4* __restrict__ gb,
      const float4* __restrict__ pl4,
      const int*    __restrict__ gl,
      const float4* __restrict__ anc,
      float* __restrict__ out)
{
    // s_mem: main phase = p_labels staging (256*21 floats = 21504 B)
    //        select phase = hist[1024] u32 (4 KB) + buf[4096] u32 (16 KB)
    __shared__ __align__(16) char s_mem[TPB * CC * 4];
    __shared__ float rs[8], rc[8];
    __shared__ int   rp[8];
    __shared__ unsigned gsum[256];
    __shared__ float a66[NBLK], c66[NBLK];
    __shared__ int   p66[NBLK];
    __shared__ float red[8];
    __shared__ unsigned s_sel, s_krem;
    __shared__ int   s_gcnt, s_lastb, s_lastg;

    const int b    = blockIdx.y;
    const int base = blockIdx.x * TPB;
    const int tid  = threadIdx.x;
    const int lane = tid & 31;
    const int n    = base + tid;
    const int cnt  = min(TPB, NN - base);

    float* s_lab = (float*)s_mem;

    // ======================= MAIN PHASE =======================
    {
        const float4* src = pl4 + ((size_t)b * NN + base) * CC / 4;
        float4* dst = (float4*)s_lab;
        const int tot4 = (cnt * CC) >> 2;
        for (int i = tid; i < tot4; i += TPB) dst[i] = src[i];
    }
    __syncthreads();

    float sl1 = 0.f, ce = 0.f;
    int pos = 0;
    if (tid < cnt) {
        float4 a = anc[n];
        float4 g = gb[b * NN + n];
        float4 p = pb[b * NN + n];
        float t0 = 10.f * (g.x - a.x) / a.z;
        float t1 = 10.f * (g.y - a.y) / a.w;
        float t2 = 5.f * __logf(g.z / a.z);
        float t3 = 5.f * __logf(g.w / a.w);
        sl1 = smooth_l1(p.x - t0) + smooth_l1(p.y - t1)
            + smooth_l1(p.z - t2) + smooth_l1(p.w - t3);

        const float* x = s_lab + tid * CC;   // stride 21, conflict-free
        float s = 0.f;
        #pragma unroll
        for (int j = 0; j < CC; j++) s += __expf(x[j]);
        int lab = gl[b * NN + n];
        ce = __logf(s) - x[lab];
        pos = (lab > 0);

        d_neg[b * NN + n] = pos ? 0.f : fmaxf(ce, 0.f);
    }

    float vsl = pos ? sl1 : 0.f;
    float vce = pos ? ce  : 0.f;
    #pragma unroll
    for (int o = 16; o; o >>= 1) {
        vsl += __shfl_down_sync(0xFFFFFFFFu, vsl, o);
        vce += __shfl_down_sync(0xFFFFFFFFu, vce, o);
    }
    int wp = __popc(__ballot_sync(0xFFFFFFFFu, pos));
    const int w = tid >> 5;
    if (lane == 0) { rs[w] = vsl; rc[w] = vce; rp[w] = wp; }
    __syncthreads();
    if (tid == 0) {
        float A = 0.f, Cc = 0.f; int P = 0;
        #pragma unroll
        for (int i = 0; i < 8; i++) { A += rs[i]; Cc += rc[i]; P += rp[i]; }
        const int idx = b * NBLK + blockIdx.x;
        d_psl1[idx] = A;
        d_pce [idx] = Cc;
        d_ppos[idx] = P;
        __threadfence();
        s_lastb = (atomicAdd(&d_btick[b], 1) == NBLK - 1);
    }
    __syncthreads();
    if (!s_lastb) return;

    // ======================= SELECT PHASE (last block of batch b) =======================
    __threadfence();
    if (tid == 0) { d_btick[b] = 0; s_gcnt = 0; }   // reset ticket for next replay

    unsigned* hist = (unsigned*)s_mem;            // 1024 u32
    unsigned* buf  = hist + SBINS;                // 4096 u32

    // load per-block partials (L2, bypass L1)
    if (tid < NBLK) {
        const int idx = b * NBLK + tid;
        a66[tid] = __ldcg(&d_psl1[idx]);
        c66[tid] = __ldcg(&d_pce [idx]);
        p66[tid] = __ldcg(&d_ppos[idx]);
    }
    // zero hist
    for (int i = tid; i < SBINS; i += TPB) hist[i] = 0u;
    __syncthreads();

    // reduce partials (warp 0)
    float lossb = 0.f, cepos = 0.f;
    int posn = 0;
    if (tid < 32) {
        float A  = a66[tid] + ((tid + 32 < NBLK) ? a66[tid + 32] : 0.f) + ((tid + 64 < NBLK) ? a66[tid + 64] : 0.f);
        float Cc = c66[tid] + ((tid + 32 < NBLK) ? c66[tid + 32] : 0.f) + ((tid + 64 < NBLK) ? c66[tid + 64] : 0.f);
        int   P  = p66[tid] + ((tid + 32 < NBLK) ? p66[tid + 32] : 0)   + ((tid + 64 < NBLK) ? p66[tid + 64] : 0);
        #pragma unroll
        for (int o = 16; o; o >>= 1) {
            A  += __shfl_down_sync(0xFFFFFFFFu, A, o);
            Cc += __shfl_down_sync(0xFFFFFFFFu, Cc, o);
            P  += __shfl_down_sync(0xFFFFFFFFu, P, o);
        }
        if (tid == 0) { rs[0] = A; rc[0] = Cc; rp[0] = P; }
    }
    __syncthreads();
    lossb = rs[0]; cepos = rc[0]; posn = rp[0];
    const int k0 = min(3 * posn, NN);

    unsigned tb = 0;
    int ties = 0;

    const uint4* src4 = (const uint4*)(d_neg + b * NN);
    const int NIT = (NN / 4 + TPB - 1) / TPB;   // 17

    if (k0 > 0) {
        // pass 1: linear-bin histogram (L2 reads)
        for (int it = 0; it < NIT; it++) {
            const int i = it * TPB + tid;
            if (i < NN / 4) {
                uint4 t = __ldcg(&src4[i]);
                atomicAdd(&hist[lin_bin(__uint_as_float(t.x))], 1u);
                atomicAdd(&hist[lin_bin(__uint_as_float(t.y))], 1u);
                atomicAdd(&hist[lin_bin(__uint_as_float(t.z))], 1u);
                atomicAdd(&hist[lin_bin(__uint_as_float(t.w))], 1u);
            }
        }
        __syncthreads();
        // locate stage-0 bin
        if (tid < 256) {
            unsigned t = 0;
            #pragma unroll
            for (int j = 0; j < 4; j++) t += hist[tid * 4 + j];
            gsum[tid] = t;
        }
        __syncthreads();
        if (tid < 32) warp_locate(hist, gsum, 4, k0, &s_sel, &s_krem);
        __syncthreads();
        const unsigned sel0 = s_sel;
        int k = (int)s_krem;

        // pass 2: gather boundary-bin candidates (counting only; order irrelevant)
        for (int it = 0; it < NIT; it++) {
            const int i = it * TPB + tid;
            const bool valid = (i < NN / 4);
            uint4 t = valid ? __ldcg(&src4[i]) : make_uint4(0u, 0u, 0u, 0u);
            unsigned v[4] = {t.x, t.y, t.z, t.w};
            #pragma unroll
            for (int c = 0; c < 4; c++) {
                const bool pred = valid && (lin_bin(__uint_as_float(v[c])) == sel0);
                unsigned bal = __ballot_sync(0xFFFFFFFFu, pred);
                if (bal) {
                    int base_ = 0;
                    if (lane == 0) base_ = atomicAdd(&s_gcnt, __popc(bal));
                    base_ = __shfl_sync(0xFFFFFFFFu, base_, 0);
                    int slot = base_ + __popc(bal & ((1u << lane) - 1));
                    if (pred && slot < CAPB) buf[slot] = v[c];
                }
            }
        }
        __syncthreads();
        const int gcnt = s_gcnt;
        const bool use_buf = (gcnt <= CAPB);

        // refinement: 4 stages x 8 bits over candidates (buf, or global fallback)
        unsigned prefix = 0;
        for (int s = 0; s < 4; s++) {
            const int shift = 24 - 8 * s;
            for (int i = tid; i < 256; i += TPB) hist[SBINS - 256 + i] = 0u;  // top 256 of hist (buf untouched)
            unsigned* h8 = hist + (SBINS - 256);
            __syncthreads();
            if (use_buf) {
                for (int i = tid; i < gcnt; i += TPB) {
                    unsigned bits = buf[i];
                    if (s == 0 || (bits >> (shift + 8)) == prefix)
                        atomicAdd(&h8[(bits >> shift) & 0xFFu], 1u);
                }
            } else {
                for (int it = 0; it < NIT; it++) {
                    const int i = it * TPB + tid;
                    if (i < NN / 4) {
                        uint4 t = __ldcg(&src4[i]);
                        unsigned v[4] = {t.x, t.y, t.z, t.w};
                        #pragma unroll
                        for (int c = 0; c < 4; c++) {
                            unsigned bits = v[c];
                            if (lin_bin(__uint_as_float(bits)) == sel0 &&
                                (s == 0 || (bits >> (shift + 8)) == prefix))
                                atomicAdd(&h8[(bits >> shift) & 0xFFu], 1u);
                        }
                    }
                }
            }
            __syncthreads();
            if (tid < 32) warp_locate(h8, h8, 1, k, &s_sel, &s_krem);
            __syncthreads();
            prefix = (prefix << 8) | s_sel;
            k = (int)s_krem;
            __syncthreads();
        }
        tb   = prefix;
        ties = k;
    }

    // pass 3: deterministic strided sum of strictly-above-threshold values
    float acc = 0.f;
    if (k0 > 0) {
        for (int it = 0; it < NIT; it++) {
            const int i = it * TPB + tid;
            if (i < NN / 4) {
                uint4 t = __ldcg(&src4[i]);
                if (t.x > tb) acc += __uint_as_float(t.x);
                if (t.y > tb) acc += __uint_as_float(t.y);
                if (t.z > tb) acc += __uint_as_float(t.z);
                if (t.w > tb) acc += __uint_as_float(t.w);
            }
        }
    }
    #pragma unroll
    for (int o = 16; o; o >>= 1) acc += __shfl_down_sync(0xFFFFFFFFu, acc, o);
    if (lane == 0) red[w] = acc;
    __syncthreads();
    if (tid == 0) {
        float negsum = 0.f;
        #pragma unroll
        for (int i = 0; i < 8; i++) negsum += red[i];
        negsum += (float)ties * __uint_as_float(tb);

        float lb = lossb;
        float ll = cepos + negsum;
        float nm = (posn > 0) ? 1.f : 0.f;
        float pf = fmaxf((float)posn, FP32_EPS);
        d_res[b * 3 + 0] = (lb + ll) * nm / pf;
        d_res[b * 3 + 1] = lb * nm / pf;
        d_res[b * 3 + 2] = ll * nm / pf;

        __threadfence();
        s_lastg = (atomicAdd(&d_done, 1) == BB - 1);
    }
    __syncthreads();

    // fused cross-batch final reduction (last batch to finish)
    if (s_lastg) {
        __threadfence();
        float lt = 0.f, vb = 0.f, vl = 0.f;
        if (tid < BB) {
            volatile float* r = d_res;
            lt = r[tid * 3 + 0];
            vb = r[tid * 3 + 1];
            vl = r[tid * 3 + 2];
        }
        if (tid < 64) {
            #pragma unroll
            for (int o = 16; o; o >>= 1) {
                lt += __shfl_down_sync(0xFFFFFFFFu, lt, o);
                vb += __shfl_down_sync(0xFFFFFFFFu, vb, o);
                vl += __shfl_down_sync(0xFFFFFFFFu, vl, o);
            }
            if ((tid & 31) == 0) {
                red[tid >> 5]       = lt;
                red[(tid >> 5) + 2] = vb;
                red[(tid >> 5) + 4] = vl;
            }
        }
        __syncthreads();
        if (tid == 0) {
            out[0] = (red[0] + red[1]) * (1.f / 64.f);
            out[1] = (red[2] + red[3]) * (1.f / 64.f);
            out[2] = (red[4] + red[5]) * (1.f / 64.f);
            d_done = 0;   // self-reset for next graph replay
        }
    }
}

// ---------------- launch ----------------
extern "C" void kernel_launch(void* const* d_in, const int* in_sizes, int n_in,
                              void* d_out, int out_size) {
    const float4* pb  = (const float4*)d_in[0];
    const float4* gb  = (const float4*)d_in[1];
    const float4* pl4 = (const float4*)d_in[2];
    const int*    gl  = (const int*)d_in[3];
    const float4* anc = (const float4*)d_in[4];
    float* out = (float*)d_out;

    dim3 gBN(NBLK, BB);
    k_all<<<gBN, TPB>>>(pb, gb, pl4, gl, anc, out);
}